// round 13
// baseline (speedup 1.0000x reference)
#include <cuda_runtime.h>
#include <cuda_bf16.h>
#include <cstdint>

// ---------------- problem constants ----------------------------------------
#define BB 2
#define LL 1024
#define DMODEL 1024
#define ED 2048
#define NSTATE 16
#define DTRANK 64
#define BL (BB*LL)          // 2048 rows
#define KSPL 8              // dbc split-K factor

// ---------------- scratch (no allocation allowed -> __device__ globals) ----
__device__ __align__(128) float g_xz[BB*LL*2*ED];
__device__ __align__(128) float g_xconv[BB*LL*ED];
__device__ __align__(128) float g_dbc[BL*96];
__device__ __align__(128) float g_dbc_part[KSPL*BL*96];
__device__ __align__(128) float g_delta[BB*LL*ED];
__device__ __align__(128) float g_out_part[2*BL*DMODEL];

// bf16 split-precision scratch
__device__ __align__(128) __nv_bfloat16 g_xh[BL*DMODEL];
__device__ __align__(128) __nv_bfloat16 g_xl[BL*DMODEL];
__device__ __align__(128) __nv_bfloat16 g_w1h[2*ED*DMODEL];
__device__ __align__(128) __nv_bfloat16 g_w1l[2*ED*DMODEL];
__device__ __align__(128) __nv_bfloat16 g_yh[BL*ED];
__device__ __align__(128) __nv_bfloat16 g_yl[BL*ED];
__device__ __align__(128) __nv_bfloat16 g_w6h[DMODEL*ED];
__device__ __align__(128) __nv_bfloat16 g_w6l[DMODEL*ED];
__device__ __align__(128) __nv_bfloat16 g_d64h[BL*DTRANK];   // dbc[:, :64] hi/lo
__device__ __align__(128) __nv_bfloat16 g_d64l[BL*DTRANK];
__device__ __align__(128) __nv_bfloat16 g_w4h[ED*DTRANK];    // dt_proj_w^T hi/lo
__device__ __align__(128) __nv_bfloat16 g_w4l[ED*DTRANK];

// persistent-GEMM work queue (self-resetting, deterministic output)
__device__ unsigned g_ticket = 0;
__device__ unsigned g_done   = 0;

// ---------------- PTX helpers (sm_80-level only: no tcgen05/TMA!) ----------
__device__ __forceinline__ uint32_t smem_u32(const void* p) {
    uint32_t a;
    asm("{ .reg .u64 t; cvta.to.shared.u64 t, %1; cvt.u32.u64 %0, t; }"
        : "=r"(a) : "l"(p));
    return a;
}

#define CP_ASYNC16(dst, src) \
    asm volatile("cp.async.cg.shared.global [%0], [%1], 16;" \
                 :: "r"(dst), "l"(src) : "memory")
#define CP_COMMIT() asm volatile("cp.async.commit_group;" ::: "memory")
#define CP_WAIT(n)  asm volatile("cp.async.wait_group %0;" :: "n"(n) : "memory")

#define LDSM_X4(r0,r1,r2,r3, addr) \
    asm volatile("ldmatrix.sync.aligned.m8n8.x4.shared.b16 {%0,%1,%2,%3}, [%4];" \
                 : "=r"(r0),"=r"(r1),"=r"(r2),"=r"(r3) : "r"(addr))

__device__ __forceinline__ void mma_bf16(float* c, const uint32_t* a, const uint32_t* b) {
    asm volatile(
        "mma.sync.aligned.m16n8k16.row.col.f32.bf16.bf16.f32 "
        "{%0,%1,%2,%3}, {%4,%5,%6,%7}, {%8,%9}, {%0,%1,%2,%3};"
        : "+f"(c[0]), "+f"(c[1]), "+f"(c[2]), "+f"(c[3])
        : "r"(a[0]), "r"(a[1]), "r"(a[2]), "r"(a[3]), "r"(b[0]), "r"(b[1]));
}

// ---------------- bf16x3 mma.sync GEMM, persistent tile loop ---------------
// CTA 128x128, BK=32, 8 warps of 64x32, 2-stage pipeline, 2 CTAs/SM.
// Tiles indexed t = x + gx*(y + gy*z); z is a K-slice (ldk row stride),
// partial output to C + z*M*N. ACT=1: +bias, softplus epilogue.
#define TPAD 40
#define TILE_B (128*TPAD*2)
#define STAGE_B (4*TILE_B)
#define GSM_BYTES (2*STAGE_B)

template<int ACT>
__global__ __launch_bounds__(256, 2)
void gemm_bf16x3(const __nv_bfloat16* __restrict__ Ah, const __nv_bfloat16* __restrict__ Al,
                 const __nv_bfloat16* __restrict__ Bh, const __nv_bfloat16* __restrict__ Bl,
                 float* __restrict__ C, int M, int N, int K, int ldk,
                 int nTiles, const float* __restrict__ bias)
{
    extern __shared__ __align__(128) char smem[];
    __shared__ unsigned s_tile;
    const uint32_t sb = smem_u32(smem);
    const int tid  = threadIdx.x;
    const int lane = tid & 31;
    const int warp = tid >> 5;
    const int wm   = warp >> 2;
    const int wn   = warp & 3;
    const int NK = K >> 5;
    const int gx = N >> 7, gy = M >> 7;

    const uint32_t aRow = (uint32_t)(wm * 64 + (lane & 15)) * (TPAD * 2)
                        + (uint32_t)(lane >> 4) * 16;
    const uint32_t bRow = (uint32_t)(wn * 32 + ((lane >> 4) & 1) * 8 + (lane & 7)) * (TPAD * 2)
                        + (uint32_t)((lane >> 3) & 1) * 16;

    for (;;) {
        if (tid == 0) s_tile = atomicAdd(&g_ticket, 1u);
        __syncthreads();
        const unsigned t = s_tile;
        if (t >= (unsigned)nTiles) break;

        const int tx = t % gx;
        const int ty = (t / gx) % gy;
        const int tz = t / (gx * gy);
        const int m0 = ty * 128, n0 = tx * 128;
        const int kz = tz * K;

        const __nv_bfloat16* gbase[4] = {
            Ah + (size_t)m0 * ldk + kz, Al + (size_t)m0 * ldk + kz,
            Bh + (size_t)n0 * ldk + kz, Bl + (size_t)n0 * ldk + kz };
        float* Cz = C + (size_t)tz * M * N;

        auto loadStage = [&](int kc) {
            const uint32_t stg = sb + (uint32_t)(kc & 1) * STAGE_B;
            const int koff = kc * 32;
            #pragma unroll
            for (int i = 0; i < 8; i++) {
                const int c  = tid + i * 256;
                const int tt = c >> 9;
                const int cc = c & 511;
                const int row = cc >> 2, q = cc & 3;
                const __nv_bfloat16* src = gbase[tt] + (size_t)row * ldk + koff + q * 8;
                const uint32_t dst = stg + tt * TILE_B + (row * TPAD + q * 8) * 2;
                CP_ASYNC16(dst, src);
            }
        };

        float acc[4][4][4];
        #pragma unroll
        for (int i = 0; i < 4; i++)
            #pragma unroll
            for (int j = 0; j < 4; j++)
                #pragma unroll
                for (int k = 0; k < 4; k++) acc[i][j][k] = 0.f;

        loadStage(0);
        CP_COMMIT();

        for (int kc = 0; kc < NK; kc++) {
            if (kc + 1 < NK) { loadStage(kc + 1); CP_COMMIT(); CP_WAIT(1); }
            else             { CP_WAIT(0); }
            __syncthreads();

            const uint32_t stg = sb + (uint32_t)(kc & 1) * STAGE_B;
            const uint32_t sAh = stg,            sAl = stg + TILE_B;
            const uint32_t sBh = stg + 2*TILE_B, sBl = stg + 3*TILE_B;

            #pragma unroll
            for (int ks = 0; ks < 2; ks++) {
                const uint32_t kOff = ks * 32;

                uint32_t bh[4][2], bl[4][2];
                #pragma unroll
                for (int p = 0; p < 2; p++) {
                    const uint32_t ro = bRow + (uint32_t)p * 16 * (TPAD * 2) + kOff;
                    LDSM_X4(bh[2*p][0], bh[2*p][1], bh[2*p+1][0], bh[2*p+1][1], sBh + ro);
                    LDSM_X4(bl[2*p][0], bl[2*p][1], bl[2*p+1][0], bl[2*p+1][1], sBl + ro);
                }
                #pragma unroll
                for (int mf = 0; mf < 4; mf++) {
                    const uint32_t ro = aRow + (uint32_t)mf * 16 * (TPAD * 2) + kOff;
                    uint32_t ah[4], al[4];
                    LDSM_X4(ah[0], ah[1], ah[2], ah[3], sAh + ro);
                    LDSM_X4(al[0], al[1], al[2], al[3], sAl + ro);
                    #pragma unroll
                    for (int nf = 0; nf < 4; nf++) {
                        mma_bf16(acc[mf][nf], ah, bh[nf]);
                        mma_bf16(acc[mf][nf], ah, bl[nf]);
                        mma_bf16(acc[mf][nf], al, bh[nf]);
                    }
                }
            }
            __syncthreads();
        }

        const int mBase = m0 + wm * 64 + (lane >> 2);
        const int nBase = n0 + wn * 32 + (lane & 3) * 2;
        #pragma unroll
        for (int mf = 0; mf < 4; mf++)
            #pragma unroll
            for (int nf = 0; nf < 4; nf++) {
                const int r = mBase + mf * 16;
                const int c = nBase + nf * 8;
                float v0 = acc[mf][nf][0], v1 = acc[mf][nf][1];
                float v2 = acc[mf][nf][2], v3 = acc[mf][nf][3];
                if (ACT == 1) {
                    const float b0 = bias[c], b1 = bias[c + 1];
                    v0 += b0; v1 += b1; v2 += b0; v3 += b1;
                    v0 = (v0 > 20.f) ? v0 : log1pf(expf(v0));
                    v1 = (v1 > 20.f) ? v1 : log1pf(expf(v1));
                    v2 = (v2 > 20.f) ? v2 : log1pf(expf(v2));
                    v3 = (v3 > 20.f) ? v3 : log1pf(expf(v3));
                }
                *(float2*)&Cz[(size_t)r * N + c]       = make_float2(v0, v1);
                *(float2*)&Cz[(size_t)(r + 8) * N + c] = make_float2(v2, v3);
            }
    }

    if (tid == 0) {
        __threadfence();
        const unsigned d = atomicAdd(&g_done, 1u);
        if (d == gridDim.x - 1) { g_done = 0; g_ticket = 0; __threadfence(); }
    }
}

// ---------------- GEMM6 partial add ----------------------------------------
__global__ void add2_kernel(const float* __restrict__ part, float* __restrict__ out, int n)
{
    const int i = blockIdx.x * blockDim.x + threadIdx.x;
    if (i >= n) return;
    out[i] = part[i] + part[(size_t)n + i];
}

// ---------------- weight transpose + bf16 hi/lo split ----------------------
__global__ void wconv_kernel(const float* __restrict__ W,
                             __nv_bfloat16* __restrict__ Th,
                             __nv_bfloat16* __restrict__ Tl, int K, int N)
{
    __shared__ float t[32][33];
    const int bx = blockIdx.x * 32;
    const int by = blockIdx.y * 32;
    const int tx = threadIdx.x, ty = threadIdx.y;
    #pragma unroll
    for (int j = 0; j < 32; j += 8)
        t[ty + j][tx] = W[(size_t)(by + ty + j) * N + bx + tx];
    __syncthreads();
    #pragma unroll
    for (int j = 0; j < 32; j += 8) {
        const float v = t[tx][ty + j];
        const __nv_bfloat16 h = __float2bfloat16(v);
        const float r = v - __bfloat162float(h);
        const size_t o = (size_t)(bx + ty + j) * K + by + tx;
        Th[o] = h;  Tl[o] = __float2bfloat16(r);
    }
}

// ---------------- activation bf16 hi/lo split ------------------------------
__global__ void aconv_kernel(const float* __restrict__ A,
                             __nv_bfloat16* __restrict__ H,
                             __nv_bfloat16* __restrict__ L, int n)
{
    const int i = blockIdx.x * blockDim.x + threadIdx.x;
    if (i >= n) return;
    const float v = A[i];
    const __nv_bfloat16 h = __float2bfloat16(v);
    H[i] = h;
    L[i] = __float2bfloat16(v - __bfloat162float(h));
}

// ---------------- dbc[:, :64] strided bf16 split ---------------------------
__global__ void d64_split_kernel(const float* __restrict__ dbc,
                                 __nv_bfloat16* __restrict__ H,
                                 __nv_bfloat16* __restrict__ L)
{
    const int i = blockIdx.x * blockDim.x + threadIdx.x;
    if (i >= BL * DTRANK) return;
    const int row = i >> 6, col = i & 63;
    const float v = dbc[(size_t)row * 96 + col];
    const __nv_bfloat16 h = __float2bfloat16(v);
    H[i] = h;
    L[i] = __float2bfloat16(v - __bfloat162float(h));
}

// ---------------- dbc split-K SGEMM ----------------------------------------
__global__ __launch_bounds__(256)
void dbc_split_kernel(const float* __restrict__ A,
                      const float* __restrict__ Bm,
                      float* __restrict__ part)
{
    constexpr int BM = 64, BN = 96, BK = 32, TM = 4, TN = 6;
    constexpr int THREADS = (BM/TM)*(BN/TN);
    constexpr int KSUB = ED / KSPL;
    __shared__ float As[BK][BM];
    __shared__ float Bs[BK][BN];

    const int tid = threadIdx.x;
    const int tx  = tid % (BN/TN);
    const int ty  = tid / (BN/TN);
    const int rowBase = blockIdx.y * BM;
    const int kBase   = blockIdx.z * KSUB;
    float* C = part + (size_t)blockIdx.z * BL * 96;

    float acc[TM][TN];
    #pragma unroll
    for (int i = 0; i < TM; i++)
        #pragma unroll
        for (int j = 0; j < TN; j++) acc[i][j] = 0.f;

    for (int k0 = 0; k0 < KSUB; k0 += BK) {
        #pragma unroll
        for (int i = 0; i < 2; i++) {
            int idx = tid + i*THREADS;
            int r  = idx / (BK/4);
            int c4 = idx % (BK/4);
            float4 v = *(const float4*)&A[(size_t)(rowBase + r)*ED + kBase + k0 + c4*4];
            As[c4*4+0][r] = v.x;
            As[c4*4+1][r] = v.y;
            As[c4*4+2][r] = v.z;
            As[c4*4+3][r] = v.w;
        }
        #pragma unroll
        for (int i = 0; i < 3; i++) {
            int idx = tid + i*THREADS;
            int r  = idx / (BN/4);
            int c4 = idx % (BN/4);
            *(float4*)&Bs[r][c4*4] =
                *(const float4*)&Bm[(size_t)(kBase + k0 + r)*96 + c4*4];
        }
        __syncthreads();

        #pragma unroll
        for (int k = 0; k < BK; k++) {
            float ra[TM], rb[TN];
            #pragma unroll
            for (int i = 0; i < TM; i++) ra[i] = As[k][ty*TM + i];
            #pragma unroll
            for (int j = 0; j < TN; j++) rb[j] = Bs[k][tx*TN + j];
            #pragma unroll
            for (int i = 0; i < TM; i++)
                #pragma unroll
                for (int j = 0; j < TN; j++)
                    acc[i][j] += ra[i]*rb[j];
        }
        __syncthreads();
    }

    #pragma unroll
    for (int i = 0; i < TM; i++) {
        int r = rowBase + ty*TM + i;
        #pragma unroll
        for (int j = 0; j < TN; j++)
            C[(size_t)r*96 + tx*TN + j] = acc[i][j];
    }
}

__global__ void dbc_reduce_kernel(const float* __restrict__ part,
                                  float* __restrict__ out)
{
    const int i = blockIdx.x * blockDim.x + threadIdx.x;
    if (i >= BL*96) return;
    float s = 0.f;
    #pragma unroll
    for (int p = 0; p < KSPL; p++) s += part[(size_t)p*BL*96 + i];
    out[i] = s;
}

// ---------------- depthwise causal conv1d + bias + SiLU (float4) -----------
__global__ void conv_silu4_kernel(const float* __restrict__ xz,
                                  const float* __restrict__ w,
                                  const float* __restrict__ bias,
                                  float* __restrict__ out)
{
    const int i = blockIdx.x * blockDim.x + threadIdx.x;
    if (i >= BB*LL*(ED/4)) return;
    const int e4 = (i % (ED/4)) * 4;
    const int l  = (i / (ED/4)) % LL;
    const int b  = i / ((ED/4)*LL);

    const float* base = xz + (size_t)b*LL*2*ED + (size_t)l*2*ED + e4;
    const float4 w0 = *(const float4*)&w[(e4+0)*4];
    const float4 w1 = *(const float4*)&w[(e4+1)*4];
    const float4 w2 = *(const float4*)&w[(e4+2)*4];
    const float4 w3 = *(const float4*)&w[(e4+3)*4];
    float4 acc = *(const float4*)&bias[e4];

    if (l >= 3) {
        const float4 v = *(const float4*)(base - 3*2*ED);
        acc.x += w0.x*v.x; acc.y += w1.x*v.y; acc.z += w2.x*v.z; acc.w += w3.x*v.w;
    }
    if (l >= 2) {
        const float4 v = *(const float4*)(base - 2*2*ED);
        acc.x += w0.y*v.x; acc.y += w1.y*v.y; acc.z += w2.y*v.z; acc.w += w3.y*v.w;
    }
    if (l >= 1) {
        const float4 v = *(const float4*)(base - 1*2*ED);
        acc.x += w0.z*v.x; acc.y += w1.z*v.y; acc.z += w2.z*v.z; acc.w += w3.z*v.w;
    }
    {
        const float4 v = *(const float4*)(base);
        acc.x += w0.w*v.x; acc.y += w1.w*v.y; acc.z += w2.w*v.z; acc.w += w3.w*v.w;
    }
    acc.x = acc.x / (1.f + __expf(-acc.x));
    acc.y = acc.y / (1.f + __expf(-acc.y));
    acc.z = acc.z / (1.f + __expf(-acc.z));
    acc.w = acc.w / (1.f + __expf(-acc.w));
    *(float4*)&out[((size_t)b*LL + l)*ED + e4] = acc;
}

// ---------------- fused selective scan v3 ----------------------------------
__global__ __launch_bounds__(128)
void scan3_kernel(const float* __restrict__ delta,
                  const float* __restrict__ dbc,
                  const float* __restrict__ xconv,
                  const float* __restrict__ xz,
                  const float* __restrict__ A_log,
                  const float* __restrict__ Dw,
                  __nv_bfloat16* __restrict__ yh,
                  __nv_bfloat16* __restrict__ yl)
{
    const int b   = blockIdx.y;
    const int tid = threadIdx.x;
    const int g   = tid & 3;
    const int ep  = tid >> 2;
    const int e   = blockIdx.x * 32 + ep;

    __shared__ __align__(16) float sBC[128][36];

    float an[4];
    bool ok = true;
    #pragma unroll
    for (int j = 0; j < 4; j++) {
        const int n = g*4 + j;
        an[j] = -__expf(A_log[e*NSTATE + n]);
        ok = ok && (fabsf(an[j] + (float)(n+1)) < 1e-4f * (float)(n+1));
    }
    const float Dval = Dw[e];

    const float* dRow   = delta + (size_t)b*LL*ED + e;
    const float* xRow   = xconv + (size_t)b*LL*ED + e;
    const float* zRow   = xz    + (size_t)b*LL*2*ED + ED + e;
    const float* bcBase = dbc   + (size_t)b*LL*96;
    __nv_bfloat16* yhRow = yh + (size_t)b*LL*ED + e;
    __nv_bfloat16* ylRow = yl + (size_t)b*LL*ED + e;

    float h[4] = {0.f, 0.f, 0.f, 0.f};

    float pd[2][4], px[2][4], pz[2][4];
    #pragma unroll
    for (int j = 0; j < 4; j++) {
        pd[0][j] = dRow[(size_t)j*ED];
        px[0][j] = xRow[(size_t)j*ED];
        pz[0][j] = zRow[(size_t)j*2*ED];
    }

    for (int gi = 0; gi < LL/4; gi++) {
        const int l0 = gi * 4;
        if ((l0 & 127) == 0) {
            __syncthreads();
            for (int i = tid; i < 128*8; i += 128) {
                const int li = i >> 3, q = i & 7;
                const float4 v = *(const float4*)&bcBase[(size_t)(l0+li)*96 + DTRANK + q*4];
                *(float4*)&sBC[li][q*4] = v;
            }
            __syncthreads();
        }
        const int cur = gi & 1, nxt = cur ^ 1;
        if (gi + 1 < LL/4) {
            const int l1 = l0 + 4;
            #pragma unroll
            for (int j = 0; j < 4; j++) {
                pd[nxt][j] = dRow[(size_t)(l1+j)*ED];
                px[nxt][j] = xRow[(size_t)(l1+j)*ED];
                pz[nxt][j] = zRow[(size_t)(l1+j)*2*ED];
            }
        }
        #pragma unroll
        for (int j = 0; j < 4; j++) {
            const int li = (l0 & 127) + j;
            const float dv = pd[cur][j], xv = px[cur][j], zv = pz[cur][j];
            const float bx = dv * xv;

            const float4 vb = *(const float4*)&sBC[li][g*4];
            const float4 vc = *(const float4*)&sBC[li][16 + g*4];

            float dA[4];
            if (ok) {
                const float t1 = __expf(-dv);
                const float t2 = t1*t1;
                const float t3 = t2*t1;
                const float t4 = t2*t2;
                float tg = 1.f;
                if (g & 1) tg *= t4;
                if (g & 2) tg *= t4*t4;
                dA[0] = tg*t1; dA[1] = tg*t2; dA[2] = tg*t3; dA[3] = tg*t4;
            } else {
                #pragma unroll
                for (int n = 0; n < 4; n++) dA[n] = __expf(dv * an[n]);
            }

            float yp = 0.f;
            h[0] = dA[0]*h[0] + bx*vb.x;  yp += h[0]*vc.x;
            h[1] = dA[1]*h[1] + bx*vb.y;  yp += h[1]*vc.y;
            h[2] = dA[2]*h[2] + bx*vb.z;  yp += h[2]*vc.z;
            h[3] = dA[3]*h[3] + bx*vb.w;  yp += h[3]*vc.w;

            yp += __shfl_xor_sync(0xffffffffu, yp, 1);
            yp += __shfl_xor_sync(0xffffffffu, yp, 2);

            if (g == 0) {
                float yv = yp + Dval * xv;
                const float sil = zv / (1.f + __expf(-zv));
                yv *= sil;
                const int l = l0 + j;
                const __nv_bfloat16 hh = __float2bfloat16(yv);
                yhRow[(size_t)l*ED] = hh;
                ylRow[(size_t)l*ED] = __float2bfloat16(yv - __bfloat162float(hh));
            }
        }
    }
}

// ---------------- launch ---------------------------------------------------
extern "C" void kernel_launch(void* const* d_in, const int* in_sizes, int n_in,
                              void* d_out, int out_size)
{
    const float* x          = (const float*)d_in[0];
    const float* in_proj_w  = (const float*)d_in[1];
    const float* conv_w     = (const float*)d_in[2];
    const float* conv_b     = (const float*)d_in[3];
    const float* x_proj_w   = (const float*)d_in[4];
    const float* dt_proj_w  = (const float*)d_in[5];
    const float* dt_proj_b  = (const float*)d_in[6];
    const float* A_log      = (const float*)d_in[7];
    const float* Dw         = (const float*)d_in[8];
    const float* out_proj_w = (const float*)d_in[9];
    float* out = (float*)d_out;

    float *xzP, *xconvP, *dbcP, *dbcPartP, *deltaP, *outPartP;
    cudaGetSymbolAddress((void**)&xzP,      g_xz);
    cudaGetSymbolAddress((void**)&xconvP,   g_xconv);
    cudaGetSymbolAddress((void**)&dbcP,     g_dbc);
    cudaGetSymbolAddress((void**)&dbcPartP, g_dbc_part);
    cudaGetSymbolAddress((void**)&deltaP,   g_delta);
    cudaGetSymbolAddress((void**)&outPartP, g_out_part);

    __nv_bfloat16 *xhP, *xlP, *w1hP, *w1lP, *yhP, *ylP, *w6hP, *w6lP;
    __nv_bfloat16 *d64hP, *d64lP, *w4hP, *w4lP;
    cudaGetSymbolAddress((void**)&xhP,   g_xh);
    cudaGetSymbolAddress((void**)&xlP,   g_xl);
    cudaGetSymbolAddress((void**)&w1hP,  g_w1h);
    cudaGetSymbolAddress((void**)&w1lP,  g_w1l);
    cudaGetSymbolAddress((void**)&yhP,   g_yh);
    cudaGetSymbolAddress((void**)&ylP,   g_yl);
    cudaGetSymbolAddress((void**)&w6hP,  g_w6h);
    cudaGetSymbolAddress((void**)&w6lP,  g_w6l);
    cudaGetSymbolAddress((void**)&d64hP, g_d64h);
    cudaGetSymbolAddress((void**)&d64lP, g_d64l);
    cudaGetSymbolAddress((void**)&w4hP,  g_w4h);
    cudaGetSymbolAddress((void**)&w4lP,  g_w4l);

    cudaFuncSetAttribute(gemm_bf16x3<0>,
                         cudaFuncAttributeMaxDynamicSharedMemorySize, GSM_BYTES);
    cudaFuncSetAttribute(gemm_bf16x3<1>,
                         cudaFuncAttributeMaxDynamicSharedMemorySize, GSM_BYTES);

    // 0) weight transpose + split (W1, W6, dt_proj_w^T)
    wconv_kernel<<<dim3(2*ED/32, DMODEL/32), dim3(32,8)>>>(in_proj_w,  w1hP, w1lP, DMODEL, 2*ED);
    wconv_kernel<<<dim3(DMODEL/32, ED/32),   dim3(32,8)>>>(out_proj_w, w6hP, w6lP, ED, DMODEL);
    wconv_kernel<<<dim3(ED/32, DTRANK/32),   dim3(32,8)>>>(dt_proj_w,  w4hP, w4lP, DTRANK, ED);

    // 0b) x split
    aconv_kernel<<<(BL*DMODEL + 255)/256, 256>>>(x, xhP, xlP, BL*DMODEL);

    // 1) xz = x @ W1 : 512 tiles, persistent 296 CTAs
    gemm_bf16x3<0><<<296, 256, GSM_BYTES>>>(
        xhP, xlP, w1hP, w1lP, xzP, BL, 2*ED, DMODEL, DMODEL, 512, nullptr);

    // 2) depthwise causal conv + SiLU -> xconv (float4)
    conv_silu4_kernel<<<(BB*LL*(ED/4) + 255)/256, 256>>>(xzP, conv_w, conv_b, xconvP);

    // 3) dbc = xconv @ x_proj_w : split-K=8 + reduce
    {
        dim3 grid(1, BL/64, KSPL);
        dbc_split_kernel<<<grid, 256>>>(xconvP, x_proj_w, dbcPartP);
        dbc_reduce_kernel<<<(BL*96 + 255)/256, 256>>>(dbcPartP, dbcP);
    }

    // 4) delta = softplus(dbc[:, :64] @ dt_proj_w + b) — bf16x3 tensor path
    d64_split_kernel<<<(BL*DTRANK + 255)/256, 256>>>(dbcP, d64hP, d64lP);
    gemm_bf16x3<1><<<256, 256, GSM_BYTES>>>(
        d64hP, d64lP, w4hP, w4lP, deltaP, BL, ED, DTRANK, DTRANK, 256, dt_proj_b);

    // 5) fused selective scan v3 -> yh/yl bf16 split
    {
        dim3 grid(ED/32, BB);
        scan3_kernel<<<grid, 128>>>(deltaP, dbcP, xconvP, xzP, A_log, Dw, yhP, ylP);
    }

    // 6) out = y @ W6 : split-K=2 (256 tiles, one wave) + add
    gemm_bf16x3<0><<<256, 256, GSM_BYTES>>>(
        yhP, ylP, w6hP, w6lP, outPartP, BL, DMODEL, ED/2, ED, 256, nullptr);
    add2_kernel<<<(BL*DMODEL + 255)/256, 256>>>(outPartP, out, BL*DMODEL);
}